// round 2
// baseline (speedup 1.0000x reference)
#include <cuda_runtime.h>
#include <cuda_bf16.h>
#include <math.h>

// Problem constants
#define B_   16
#define T_   512
#define C_   8
#define S_   64
#define KSZ_ 32
#define TOUT_ 481   // T - KSZ + 1

// Scratch (no allocations allowed in kernel_launch)
__device__ float g_xmean[B_ * C_];
__device__ float g_xrstd[B_ * C_];
// Packed kernel constants, per k (KSZ index):
//   g_kq[k*512 + sp*16 + i*2 + half] = -2 * kern_norm[s = 2*sp + half][k][i]
//   (pairs of s interleaved elementwise -> ready-made f32x2 operands)
__device__ __align__(16) float g_kq[KSZ_ * 32 * 16];   // 32x32x16 = 16384 floats
//   g_kc[k*64 + sp*2 + half] = sum_c kern_norm[s][k][c]^2
__device__ __align__(8) float g_kc[KSZ_ * S_];         // 2048 floats

// ---------------------------------------------------------------------------
// Kernel 1: stats + kernel normalization/reorder.
//   blocks [0,128): per-(b,c) mean/rstd of x over T
//   blocks [128,192): per-filter (s) normalization over KSZ*C = 256 elements,
//                     write packed-interleaved K' and per-(k,s) ||K||^2.
// ---------------------------------------------------------------------------
__global__ void lsd_stats_kernel(const float* __restrict__ x,
                                 const float* __restrict__ kern) {
    __shared__ float s1[256];
    __shared__ float s2[256];
    __shared__ float s_mean, s_rstd;
    int tid = threadIdx.x;

    if (blockIdx.x < 128) {
        // x stats for (b, c) over T = 512 samples
        int b = blockIdx.x >> 3;
        int c = blockIdx.x & 7;
        const float* xp = x + (size_t)b * T_ * C_ + c;
        float v0 = xp[(size_t)tid * C_];
        float v1 = xp[(size_t)(tid + 256) * C_];
        s1[tid] = v0 + v1;
        s2[tid] = v0 * v0 + v1 * v1;
        __syncthreads();
        #pragma unroll
        for (int o = 128; o > 0; o >>= 1) {
            if (tid < o) { s1[tid] += s1[tid + o]; s2[tid] += s2[tid + o]; }
            __syncthreads();
        }
        if (tid == 0) {
            float mean = s1[0] * (1.0f / T_);
            float var  = s2[0] * (1.0f / T_) - mean * mean;
            float std  = sqrtf(fmaxf(var, 0.0f)) + 1e-8f;
            g_xmean[b * C_ + c] = mean;
            g_xrstd[b * C_ + c] = 1.0f / std;
        }
    } else {
        // Filter s: normalize over its 256 elements (KSZ*C), one per thread.
        int s = blockIdx.x - 128;
        const float* kp = kern + (size_t)s * KSZ_ * C_;
        float v = kp[tid];
        s1[tid] = v;
        s2[tid] = v * v;
        __syncthreads();
        #pragma unroll
        for (int o = 128; o > 0; o >>= 1) {
            if (tid < o) { s1[tid] += s1[tid + o]; s2[tid] += s2[tid + o]; }
            __syncthreads();
        }
        if (tid == 0) {
            float mean = s1[0] * (1.0f / 256.0f);
            float var  = s2[0] * (1.0f / 256.0f) - mean * mean;
            float std  = sqrtf(fmaxf(var, 0.0f)) + 1e-8f;
            s_mean = mean;
            s_rstd = 1.0f / std;
        }
        __syncthreads();

        float norm = (v - s_mean) * s_rstd;
        int k = tid >> 3;       // KSZ index
        int c = tid & 7;        // channel
        int sp = s >> 1;
        int half = s & 1;
        g_kq[k * 512 + sp * 16 + c * 2 + half] = -2.0f * norm;

        // per-(k,s) sum of squares: segmented reduce over the 8 channel lanes
        float nsq = norm * norm;
        nsq += __shfl_down_sync(0xffffffffu, nsq, 4, 8);
        nsq += __shfl_down_sync(0xffffffffu, nsq, 2, 8);
        nsq += __shfl_down_sync(0xffffffffu, nsq, 1, 8);
        if (c == 0) g_kc[k * 64 + sp * 2 + half] = nsq;
    }
}

// ---------------------------------------------------------------------------
// Kernel 2: main distance + min, f32x2-packed over pairs of s.
// Block = (32 lanes = t) x (32 warps = k). Grid = (16 t-blocks, 16 batches).
// p[i] = x_norm[b, t + 8*(k%4) + i, k/4]   (8 consecutive times, 1 channel)
// out[b,t,k] = ||p||^2 + min_s ( ||K_s||^2 + sum_i p[i] * (-2 K_s[i]) )
// ---------------------------------------------------------------------------
__device__ __forceinline__ unsigned long long fma2(unsigned long long a,
                                                   unsigned long long b,
                                                   unsigned long long c) {
    unsigned long long d;
    asm("fma.rn.f32x2 %0, %1, %2, %3;" : "=l"(d) : "l"(a), "l"(b), "l"(c));
    return d;
}

__global__ void __launch_bounds__(1024, 2)
lsd_main_kernel(const float* __restrict__ x, float* __restrict__ out) {
    __shared__ float sx[C_][65];     // padded: conflict-free fill & read
    __shared__ float so[32][33];     // output staging for coalesced stores

    int tx = threadIdx.x;            // lane -> local t
    int ty = threadIdx.y;            // warp -> k
    int tid = ty * 32 + tx;
    int b = blockIdx.y;
    int t_base = blockIdx.x * 32;

    // Fill normalized x window: times [t_base, t_base+63], all 8 channels.
    if (tid < 512) {
        int tl = tid >> 3;
        int c  = tid & 7;
        float v = 0.0f;
        if (t_base + tl < T_) {
            v = x[((size_t)b * T_ + t_base) * C_ + tid];
            v = (v - g_xmean[b * C_ + c]) * g_xrstd[b * C_ + c];
        }
        sx[c][tl] = v;
    }
    __syncthreads();

    int k  = ty;
    int cx = k >> 2;
    int m  = k & 3;
    int base = tx + m * 8;

    // Patch values (registers) + ||p||^2 + packed {p,p} operands
    float p[8];
    float pnorm = 0.0f;
    unsigned long long pp[8];
    #pragma unroll
    for (int i = 0; i < 8; i++) {
        p[i] = sx[cx][base + i];
        pnorm = fmaf(p[i], p[i], pnorm);
        unsigned int u = __float_as_uint(p[i]);
        pp[i] = ((unsigned long long)u << 32) | u;   // {p, p}
    }

    const ulonglong2* kq = (const ulonglong2*)(g_kq + (size_t)k * 512);
    const unsigned long long* kc = (const unsigned long long*)(g_kc + (size_t)k * 64);

    float mn0 = 3.402823466e38f;
    float mn1 = 3.402823466e38f;
    #pragma unroll 4
    for (int sp = 0; sp < 32; sp++) {
        unsigned long long d = kc[sp];          // {c_{2sp}, c_{2sp+1}}
        ulonglong2 q0 = kq[4 * sp + 0];         // pairs i=0,1
        ulonglong2 q1 = kq[4 * sp + 1];         // pairs i=2,3
        ulonglong2 q2 = kq[4 * sp + 2];         // pairs i=4,5
        ulonglong2 q3 = kq[4 * sp + 3];         // pairs i=6,7
        d = fma2(pp[0], q0.x, d);
        d = fma2(pp[1], q0.y, d);
        d = fma2(pp[2], q1.x, d);
        d = fma2(pp[3], q1.y, d);
        d = fma2(pp[4], q2.x, d);
        d = fma2(pp[5], q2.y, d);
        d = fma2(pp[6], q3.x, d);
        d = fma2(pp[7], q3.y, d);
        float lo = __uint_as_float((unsigned int)d);
        float hi = __uint_as_float((unsigned int)(d >> 32));
        mn0 = fminf(mn0, lo);
        mn1 = fminf(mn1, hi);
    }

    so[k][tx] = pnorm + fminf(mn0, mn1);
    __syncthreads();

    // Coalesced write: warp ty handles t = t_base + ty, lanes span k.
    int t = t_base + ty;
    if (t < TOUT_) {
        out[((size_t)b * TOUT_ + t) * KSZ_ + tx] = so[tx][ty];
    }
}

extern "C" void kernel_launch(void* const* d_in, const int* in_sizes, int n_in,
                              void* d_out, int out_size) {
    const float* x    = (const float*)d_in[0];   // (16, 512, 8)
    const float* kern = (const float*)d_in[1];   // (64, 32, 8)
    float* out = (float*)d_out;                  // (16, 481, 32)

    lsd_stats_kernel<<<192, 256>>>(x, kern);

    dim3 grid(16, 16);   // (t-blocks, batch)
    dim3 blk(32, 32);
    lsd_main_kernel<<<grid, blk>>>(x, out);
}

// round 4
// speedup vs baseline: 1.4038x; 1.4038x over previous
#include <cuda_runtime.h>
#include <cuda_bf16.h>
#include <math.h>

// Problem constants
#define B_   16
#define T_   512
#define C_   8
#define S_   64
#define KSZ_ 32
#define TOUT_ 481   // T - KSZ + 1
#define KPB_ 16     // k values per block in main kernel

// Scratch (no allocations allowed in kernel_launch)
__device__ float g_xmean[B_ * C_];
__device__ float g_xrstd[B_ * C_];
// Packed kernel constants, per k (KSZ index):
//   g_kq[k*512 + sp*16 + i*2 + half] = -2 * kern_norm[s = 2*sp + half][k][i]
//   (pairs of s interleaved elementwise -> ready-made f32x2 operands)
__device__ __align__(16) float g_kq[KSZ_ * 32 * 16];   // 16384 floats
//   g_kc[k*64 + sp*2 + half] = sum_c kern_norm[s][k][c]^2
__device__ __align__(16) float g_kc[KSZ_ * S_];        // 2048 floats

// ---------------------------------------------------------------------------
// Warp-shuffle full reduction helpers
// ---------------------------------------------------------------------------
__device__ __forceinline__ void warp_red2(float& a, float& b) {
    #pragma unroll
    for (int o = 16; o > 0; o >>= 1) {
        a += __shfl_xor_sync(0xffffffffu, a, o);
        b += __shfl_xor_sync(0xffffffffu, b, o);
    }
}

// ---------------------------------------------------------------------------
// Kernel 1: stats + kernel normalization/reorder.
//   blocks [0,128): per-(b,c) mean/rstd of x over T
//   blocks [128,192): per-filter (s) normalization over KSZ*C = 256 elements,
//                     write packed-interleaved K' and per-(k,s) ||K||^2.
// ---------------------------------------------------------------------------
__global__ void lsd_stats_kernel(const float* __restrict__ x,
                                 const float* __restrict__ kern) {
    __shared__ float r1[8];
    __shared__ float r2[8];
    __shared__ float s_mean, s_rstd;
    int tid = threadIdx.x;
    int wid = tid >> 5;
    int lid = tid & 31;

    if (blockIdx.x < 128) {
        // x stats for (b, c) over T = 512 samples
        int b = blockIdx.x >> 3;
        int c = blockIdx.x & 7;
        const float* xp = x + (size_t)b * T_ * C_ + c;
        float v0 = xp[(size_t)tid * C_];
        float v1 = xp[(size_t)(tid + 256) * C_];
        float sum = v0 + v1;
        float sq  = v0 * v0 + v1 * v1;
        warp_red2(sum, sq);
        if (lid == 0) { r1[wid] = sum; r2[wid] = sq; }
        __syncthreads();
        if (wid == 0) {
            float a = (lid < 8) ? r1[lid] : 0.0f;
            float bq = (lid < 8) ? r2[lid] : 0.0f;
            #pragma unroll
            for (int o = 4; o > 0; o >>= 1) {
                a  += __shfl_xor_sync(0xffffffffu, a, o);
                bq += __shfl_xor_sync(0xffffffffu, bq, o);
            }
            if (lid == 0) {
                float mean = a * (1.0f / T_);
                float var  = bq * (1.0f / T_) - mean * mean;
                float std  = sqrtf(fmaxf(var, 0.0f)) + 1e-8f;
                g_xmean[b * C_ + c] = mean;
                g_xrstd[b * C_ + c] = 1.0f / std;
            }
        }
    } else {
        // Filter s: normalize over its 256 elements (KSZ*C), one per thread.
        int s = blockIdx.x - 128;
        const float* kp = kern + (size_t)s * KSZ_ * C_;
        float v = kp[tid];
        float sum = v, sq = v * v;
        warp_red2(sum, sq);
        if (lid == 0) { r1[wid] = sum; r2[wid] = sq; }
        __syncthreads();
        if (tid == 0) {
            float a = 0.0f, bq = 0.0f;
            #pragma unroll
            for (int j = 0; j < 8; j++) { a += r1[j]; bq += r2[j]; }
            float mean = a * (1.0f / 256.0f);
            float var  = bq * (1.0f / 256.0f) - mean * mean;
            float std  = sqrtf(fmaxf(var, 0.0f)) + 1e-8f;
            s_mean = mean;
            s_rstd = 1.0f / std;
        }
        __syncthreads();

        float norm = (v - s_mean) * s_rstd;
        int k = tid >> 3;       // KSZ index
        int c = tid & 7;        // channel
        int sp = s >> 1;
        int half = s & 1;
        g_kq[k * 512 + sp * 16 + c * 2 + half] = -2.0f * norm;

        // per-(k,s) sum of squares: segmented reduce over the 8 channel lanes
        float nsq = norm * norm;
        nsq += __shfl_down_sync(0xffffffffu, nsq, 4, 8);
        nsq += __shfl_down_sync(0xffffffffu, nsq, 2, 8);
        nsq += __shfl_down_sync(0xffffffffu, nsq, 1, 8);
        if (c == 0) g_kc[k * 64 + sp * 2 + half] = nsq;
    }
}

// ---------------------------------------------------------------------------
// Kernel 2: main distance + min, f32x2-packed over pairs of s, kernel table
// staged in shared memory (warp-uniform broadcast LDS instead of LDG).
// Block = (32 lanes = t) x (16 warps = k). Grid = (16 t, 2 k-chunks, 16 b).
// p[i] = x_norm[b, t + 8*(k%4) + i, k/4]
// out[b,t,k] = ||p||^2 + min_s ( ||K_s||^2 + sum_i p[i] * (-2 K_s[i]) )
// ---------------------------------------------------------------------------
__device__ __forceinline__ unsigned long long fma2(unsigned long long a,
                                                   unsigned long long b,
                                                   unsigned long long c) {
    unsigned long long d;
    asm("fma.rn.f32x2 %0, %1, %2, %3;" : "=l"(d) : "l"(a), "l"(b), "l"(c));
    return d;
}

__global__ void __launch_bounds__(512, 2)
lsd_main_kernel(const float* __restrict__ x, float* __restrict__ out) {
    __shared__ float sx[C_][65];                       // x window (padded)
    __shared__ __align__(16) float skq[KPB_][512];     // kernel table slice
    __shared__ __align__(16) float skc[KPB_][64];      // ||K||^2 slice
    __shared__ float so[32][17];                       // output staging

    int tx = threadIdx.x;            // lane -> local t
    int ty = threadIdx.y;            // warp -> local k
    int tid = ty * 32 + tx;
    int b = blockIdx.z;
    int t_base = blockIdx.x * 32;
    int k_base = blockIdx.y * KPB_;

    // Fill normalized x window: times [t_base, t_base+63], all 8 channels.
    {
        int tl = tid >> 3;
        int c  = tid & 7;
        float v = 0.0f;
        if (t_base + tl < T_) {
            v = x[((size_t)b * T_ + t_base) * C_ + tid];
            v = (v - g_xmean[b * C_ + c]) * g_xrstd[b * C_ + c];
        }
        sx[c][tl] = v;
    }
    // Stage kernel tables into shared: 16 k slices.
    {
        const float4* src = (const float4*)(g_kq + (size_t)k_base * 512);
        float4* dst = (float4*)(&skq[0][0]);
        #pragma unroll
        for (int i = 0; i < 4; i++) dst[tid + 512 * i] = src[tid + 512 * i];
        if (tid < 256) {
            const float4* srcc = (const float4*)(g_kc + (size_t)k_base * 64);
            ((float4*)(&skc[0][0]))[tid] = srcc[tid];
        }
    }
    __syncthreads();

    int k  = k_base + ty;
    int cx = k >> 2;
    int m  = k & 3;
    int base = tx + m * 8;

    // Patch values + ||p||^2 + packed {p,p} operands
    float pnorm = 0.0f;
    unsigned long long pp[8];
    #pragma unroll
    for (int i = 0; i < 8; i++) {
        float p = sx[cx][base + i];
        pnorm = fmaf(p, p, pnorm);
        unsigned int u = __float_as_uint(p);
        pp[i] = ((unsigned long long)u << 32) | u;   // {p, p}
    }

    const ulonglong2* kq = (const ulonglong2*)(&skq[ty][0]);
    const unsigned long long* kc = (const unsigned long long*)(&skc[ty][0]);

    float mn0 = 3.402823466e38f;
    float mn1 = 3.402823466e38f;
    #pragma unroll
    for (int sp = 0; sp < 32; sp++) {
        unsigned long long d = kc[sp];          // {c_{2sp}, c_{2sp+1}}
        ulonglong2 q0 = kq[4 * sp + 0];
        ulonglong2 q1 = kq[4 * sp + 1];
        ulonglong2 q2 = kq[4 * sp + 2];
        ulonglong2 q3 = kq[4 * sp + 3];
        d = fma2(pp[0], q0.x, d);
        d = fma2(pp[1], q0.y, d);
        d = fma2(pp[2], q1.x, d);
        d = fma2(pp[3], q1.y, d);
        d = fma2(pp[4], q2.x, d);
        d = fma2(pp[5], q2.y, d);
        d = fma2(pp[6], q3.x, d);
        d = fma2(pp[7], q3.y, d);
        float lo = __uint_as_float((unsigned int)d);
        float hi = __uint_as_float((unsigned int)(d >> 32));
        mn0 = fminf(mn0, lo);
        mn1 = fminf(mn1, hi);
    }

    so[tx][ty] = pnorm + fminf(mn0, mn1);
    __syncthreads();

    // Coalesced write: row r = local t, 16 consecutive k per half-warp.
    {
        int r = tid >> 4;            // local t row
        int c = tid & 15;            // local k col
        int t = t_base + r;
        if (t < TOUT_) {
            out[((size_t)b * TOUT_ + t) * KSZ_ + k_base + c] = so[r][c];
        }
    }
}

extern "C" void kernel_launch(void* const* d_in, const int* in_sizes, int n_in,
                              void* d_out, int out_size) {
    const float* x    = (const float*)d_in[0];   // (16, 512, 8)
    const float* kern = (const float*)d_in[1];   // (64, 32, 8)
    float* out = (float*)d_out;                  // (16, 481, 32)

    lsd_stats_kernel<<<192, 256>>>(x, kern);

    dim3 grid(16, 2, 16);   // (t-blocks, k-chunks, batch)
    dim3 blk(32, 16);
    lsd_main_kernel<<<grid, blk>>>(x, out);
}

// round 6
// speedup vs baseline: 2.1056x; 1.5000x over previous
#include <cuda_runtime.h>
#include <cuda_bf16.h>
#include <math.h>

// Problem constants
#define B_   16
#define T_   512
#define C_   8
#define S_   64
#define KSZ_ 32
#define TOUT_ 481   // T - KSZ + 1

// Scratch (no allocations allowed in kernel_launch)
__device__ float g_xmean[B_ * C_];
__device__ float g_xrstd[B_ * C_];
// Packed kernel constants, per k (KSZ index):
//   g_kq[k*512 + sp*16 + i*2 + half] = -2 * kern_norm[s = 2*sp + half][k][i]
__device__ __align__(16) float g_kq[KSZ_ * 32 * 16];   // 16384 floats
//   g_kc[k*64 + sp*2 + half] = sum_c kern_norm[s][k][c]^2
__device__ __align__(16) float g_kc[KSZ_ * S_];        // 2048 floats

// ---------------------------------------------------------------------------
__device__ __forceinline__ void warp_red2(float& a, float& b) {
    #pragma unroll
    for (int o = 16; o > 0; o >>= 1) {
        a += __shfl_xor_sync(0xffffffffu, a, o);
        b += __shfl_xor_sync(0xffffffffu, b, o);
    }
}

// ---------------------------------------------------------------------------
// Kernel 1: stats + kernel normalization/reorder. (unchanged, verified)
// ---------------------------------------------------------------------------
__global__ void lsd_stats_kernel(const float* __restrict__ x,
                                 const float* __restrict__ kern) {
    __shared__ float r1[8];
    __shared__ float r2[8];
    __shared__ float s_mean, s_rstd;
    int tid = threadIdx.x;
    int wid = tid >> 5;
    int lid = tid & 31;

    if (blockIdx.x < 128) {
        int b = blockIdx.x >> 3;
        int c = blockIdx.x & 7;
        const float* xp = x + (size_t)b * T_ * C_ + c;
        float v0 = xp[(size_t)tid * C_];
        float v1 = xp[(size_t)(tid + 256) * C_];
        float sum = v0 + v1;
        float sq  = v0 * v0 + v1 * v1;
        warp_red2(sum, sq);
        if (lid == 0) { r1[wid] = sum; r2[wid] = sq; }
        __syncthreads();
        if (wid == 0) {
            float a = (lid < 8) ? r1[lid] : 0.0f;
            float bq = (lid < 8) ? r2[lid] : 0.0f;
            #pragma unroll
            for (int o = 4; o > 0; o >>= 1) {
                a  += __shfl_xor_sync(0xffffffffu, a, o);
                bq += __shfl_xor_sync(0xffffffffu, bq, o);
            }
            if (lid == 0) {
                float mean = a * (1.0f / T_);
                float var  = bq * (1.0f / T_) - mean * mean;
                float std  = sqrtf(fmaxf(var, 0.0f)) + 1e-8f;
                g_xmean[b * C_ + c] = mean;
                g_xrstd[b * C_ + c] = 1.0f / std;
            }
        }
    } else {
        int s = blockIdx.x - 128;
        const float* kp = kern + (size_t)s * KSZ_ * C_;
        float v = kp[tid];
        float sum = v, sq = v * v;
        warp_red2(sum, sq);
        if (lid == 0) { r1[wid] = sum; r2[wid] = sq; }
        __syncthreads();
        if (tid == 0) {
            float a = 0.0f, bq = 0.0f;
            #pragma unroll
            for (int j = 0; j < 8; j++) { a += r1[j]; bq += r2[j]; }
            float mean = a * (1.0f / 256.0f);
            float var  = bq * (1.0f / 256.0f) - mean * mean;
            float std  = sqrtf(fmaxf(var, 0.0f)) + 1e-8f;
            s_mean = mean;
            s_rstd = 1.0f / std;
        }
        __syncthreads();

        float norm = (v - s_mean) * s_rstd;
        int k = tid >> 3;
        int c = tid & 7;
        int sp = s >> 1;
        int half = s & 1;
        g_kq[k * 512 + sp * 16 + c * 2 + half] = -2.0f * norm;

        float nsq = norm * norm;
        nsq += __shfl_down_sync(0xffffffffu, nsq, 4, 8);
        nsq += __shfl_down_sync(0xffffffffu, nsq, 2, 8);
        nsq += __shfl_down_sync(0xffffffffu, nsq, 1, 8);
        if (c == 0) g_kc[k * 64 + sp * 2 + half] = nsq;
    }
}

// ---------------------------------------------------------------------------
// Kernel 2: block = (1 k) x (256 t) x (full s). 4 warps split s-range (8 sp
// each); each lane produces 8 consecutive t from a 15-sample register window.
// Grid: (32 k, 2 t-chunks, 16 b) = 1024 blocks of 128 threads.
// ---------------------------------------------------------------------------
__device__ __forceinline__ unsigned long long fma2(unsigned long long a,
                                                   unsigned long long b,
                                                   unsigned long long c) {
    unsigned long long d;
    asm("fma.rn.f32x2 %0, %1, %2, %3;" : "=l"(d) : "l"(a), "l"(b), "l"(c));
    return d;
}

#define SXP_IDX(v) ((v) + ((v) >> 3))   // skewed layout: stride-8 -> stride-9

__global__ void __launch_bounds__(128, 5)
lsd_main_kernel(const float* __restrict__ x, float* __restrict__ out) {
    __shared__ float sxp[324];                        // skewed window (287 -> 322 used)
    __shared__ __align__(16) float skq[512];          // this k's packed table
    __shared__ __align__(16) float skc[64];           // this k's ||K||^2 pairs
    __shared__ float so[4][264];                      // per-warp partial mins

    int tid = threadIdx.x;
    int w   = tid >> 5;          // warp -> sp quarter
    int l   = tid & 31;          // lane
    int k   = blockIdx.x;
    int t0  = blockIdx.y << 8;   // 0 or 256
    int b   = blockIdx.z;

    int cx = k >> 2;
    int m  = k & 3;

    // --- stage x window (one channel), normalized, into skewed smem ---
    {
        float mean = g_xmean[b * C_ + cx];
        float rstd = g_xrstd[b * C_ + cx];
        #pragma unroll
        for (int rep = 0; rep < 3; rep++) {
            int j = tid + rep * 128;
            if (j < 287) {
                float v = 0.0f;
                int tg = t0 + j;
                if (tg < T_) v = (x[((size_t)b * T_ + tg) * C_ + cx] - mean) * rstd;
                sxp[SXP_IDX(j)] = v;
            }
        }
    }
    // --- stage this k's kernel table ---
    {
        const float4* src = (const float4*)(g_kq + (size_t)k * 512);
        ((float4*)skq)[tid] = src[tid];
        if (tid < 16) ((float4*)skc)[tid] = ((const float4*)(g_kc + (size_t)k * 64))[tid];
    }
    __syncthreads();

    // --- per-lane register window: 15 packed {v,v} covering 8 patches ---
    int base = l * 8 + m * 8;
    unsigned long long w2[15];
    float pn[8];
    #pragma unroll
    for (int v = 0; v < 15; v++) {
        float f = sxp[SXP_IDX(base + v)];
        unsigned int u = __float_as_uint(f);
        w2[v] = ((unsigned long long)u << 32) | u;
    }
    #pragma unroll
    for (int j = 0; j < 8; j++) {
        float acc = 0.0f;
        #pragma unroll
        for (int i = 0; i < 8; i++) {
            float f = __uint_as_float((unsigned int)w2[j + i]);
            acc = fmaf(f, f, acc);
        }
        pn[j] = acc;   // ||p||^2 for local t = l*8 + j
    }

    // --- main loop: this warp's 8 sp (16 s values) ---
    const ulonglong2* kq2 = (const ulonglong2*)skq;     // idx: sp*4 + q
    const unsigned long long* kcp = (const unsigned long long*)skc;

    float mn[8];
    #pragma unroll
    for (int j = 0; j < 8; j++) mn[j] = 3.402823466e38f;

    #pragma unroll
    for (int spq = 0; spq < 8; spq++) {
        int sp = (w << 3) + spq;
        ulonglong2 q0 = kq2[sp * 4 + 0];
        ulonglong2 q1 = kq2[sp * 4 + 1];
        ulonglong2 q2 = kq2[sp * 4 + 2];
        ulonglong2 q3 = kq2[sp * 4 + 3];
        unsigned long long c0 = kcp[sp];
        #pragma unroll
        for (int j = 0; j < 8; j++) {
            unsigned long long d = c0;
            d = fma2(w2[j + 0], q0.x, d);
            d = fma2(w2[j + 1], q0.y, d);
            d = fma2(w2[j + 2], q1.x, d);
            d = fma2(w2[j + 3], q1.y, d);
            d = fma2(w2[j + 4], q2.x, d);
            d = fma2(w2[j + 5], q2.y, d);
            d = fma2(w2[j + 6], q3.x, d);
            d = fma2(w2[j + 7], q3.y, d);
            float lo = __uint_as_float((unsigned int)d);
            float hi = __uint_as_float((unsigned int)(d >> 32));
            mn[j] = fminf(mn[j], fminf(lo, hi));
        }
    }

    // --- partial mins -> smem (conflict-free: so[w][j*33 + l]) ---
    #pragma unroll
    for (int j = 0; j < 8; j++) {
        so[w][j * 33 + l] = pn[j] + mn[j];
    }
    __syncthreads();

    // --- combine 4 warps' s-partials, store (2 t per thread) ---
    #pragma unroll
    for (int rep = 0; rep < 2; rep++) {
        int tt = tid + rep * 128;        // local t
        int t = t0 + tt;
        if (t < TOUT_) {
            int jj = tt & 7;
            int ll = tt >> 3;
            int idx = jj * 33 + ll;
            float v = fminf(fminf(so[0][idx], so[1][idx]),
                            fminf(so[2][idx], so[3][idx]));
            out[((size_t)b * TOUT_ + t) * KSZ_ + k] = v;
        }
    }
}

extern "C" void kernel_launch(void* const* d_in, const int* in_sizes, int n_in,
                              void* d_out, int out_size) {
    const float* x    = (const float*)d_in[0];   // (16, 512, 8)
    const float* kern = (const float*)d_in[1];   // (64, 32, 8)
    float* out = (float*)d_out;                  // (16, 481, 32)

    lsd_stats_kernel<<<192, 256>>>(x, kern);

    dim3 grid(32, 2, 16);   // (k, t-chunks, batch)
    lsd_main_kernel<<<grid, 128>>>(x, out);
}